// round 1
// baseline (speedup 1.0000x reference)
#include <cuda_runtime.h>
#include <cstdint>
#include <cstddef>

// ---------------- problem constants ----------------
#define NTOK   98304      // 32768 * 3 tokens
#define DIM_D  256
#define DIM_E  512
#define DIM_H  512
#define DIM_C  64
#define NCODES 1024
#define DECAY_F 0.99f

// ---------------- scratch (device globals; no allocs allowed) ----------------
__device__ float g_bufA[NTOK * DIM_E];     // 201 MB
__device__ float g_bufB[NTOK * DIM_H];     // 201 MB
__device__ float g_latent[NTOK * DIM_C];   // 25 MB
__device__ float g_dw[DIM_C * NCODES];
__device__ unsigned int g_counts[NCODES];
__device__ float g_norms[NCODES];
__device__ float g_loss[1];

// ---------------- f32x2 packed-FP32 helpers (Blackwell FFMA2 path) ----------------
__device__ __forceinline__ unsigned long long pack2(float lo, float hi) {
    unsigned long long r;
    asm("mov.b64 %0, {%1, %2};" : "=l"(r) : "f"(lo), "f"(hi));
    return r;
}
__device__ __forceinline__ unsigned long long fma2(unsigned long long a,
                                                   unsigned long long b,
                                                   unsigned long long c) {
    unsigned long long d;
    asm("fma.rn.f32x2 %0, %1, %2, %3;" : "=l"(d) : "l"(a), "l"(b), "l"(c));
    return d;
}
__device__ __forceinline__ float2 unpack2(unsigned long long v) {
    float lo, hi;
    asm("mov.b64 {%0, %1}, %2;" : "=f"(lo), "=f"(hi) : "l"(v));
    return make_float2(lo, hi);
}

__device__ __forceinline__ float gelu_tanh(float x) {
    // jax.nn.gelu approximate=True: 0.5*x*(1+tanh(sqrt(2/pi)*(x+0.044715*x^3)))
    float x3 = x * x * x;
    float t = tanhf(0.7978845608028654f * (x + 0.044715f * x3));
    return 0.5f * x * (1.0f + t);
}

// ---------------- fused SGEMM + bias + gelu ----------------
// C[M,N] = gelu(A[M,K] @ W[K,N] + bias[N]), all fp32 row-major.
// BM=128, BK=16, 256 threads, per-thread 8 rows x TN cols, n-pair packed f32x2 accs.
template <int BN, int TN>
__global__ void __launch_bounds__(256, 2)
sgemm_bias_gelu(const float* __restrict__ A, const float* __restrict__ W,
                const float* __restrict__ bias, float* __restrict__ O,
                int M, int Nn, int Kd) {
    constexpr int BM = 128, BK = 16;
    __shared__ __align__(16) float As[BK][BM + 4];   // transposed: As[k][m]
    __shared__ __align__(16) float Bs[BK][BN + 4];   // natural:   Bs[k][n]

    const int tid = threadIdx.x;
    const int tx = tid & 15;        // column group
    const int ty = tid >> 4;        // row group
    const int rowBase = blockIdx.y * BM;
    const int colBase = blockIdx.x * BN;

    unsigned long long acc[8][TN / 2];
#pragma unroll
    for (int m = 0; m < 8; m++)
#pragma unroll
        for (int n = 0; n < TN / 2; n++) acc[m][n] = 0ull;

    for (int k0 = 0; k0 < Kd; k0 += BK) {
        // load A tile (128x16) transposed into smem, float4 global loads
#pragma unroll
        for (int it = 0; it < 2; it++) {
            int idx = tid + it * 256;            // 512 float4 total
            int row = idx >> 2;                  // 0..127
            int kq = idx & 3;                    // 0..3
            float4 v = *reinterpret_cast<const float4*>(
                &A[(size_t)(rowBase + row) * Kd + k0 + kq * 4]);
            As[kq * 4 + 0][row] = v.x;
            As[kq * 4 + 1][row] = v.y;
            As[kq * 4 + 2][row] = v.z;
            As[kq * 4 + 3][row] = v.w;
        }
        // load W tile (16xBN), coalesced float4
        constexpr int BITERS = (BK * BN) / (4 * 256);  // 2 for BN=128, 1 for BN=64
#pragma unroll
        for (int it = 0; it < BITERS; it++) {
            int idx = tid + it * 256;
            int krow = idx / (BN / 4);
            int nq = idx % (BN / 4);
            float4 v = *reinterpret_cast<const float4*>(
                &W[(size_t)(k0 + krow) * Nn + colBase + nq * 4]);
            *reinterpret_cast<float4*>(&Bs[krow][nq * 4]) = v;
        }
        __syncthreads();

#pragma unroll
        for (int kk = 0; kk < BK; kk++) {
            float4 a0 = *reinterpret_cast<const float4*>(&As[kk][ty * 8]);
            float4 a1 = *reinterpret_cast<const float4*>(&As[kk][ty * 8 + 4]);
            float av[8] = {a0.x, a0.y, a0.z, a0.w, a1.x, a1.y, a1.z, a1.w};
            unsigned long long b2[TN / 2];
            float4 bv0 = *reinterpret_cast<const float4*>(&Bs[kk][tx * TN]);
            b2[0] = pack2(bv0.x, bv0.y);
            b2[1] = pack2(bv0.z, bv0.w);
            if constexpr (TN == 8) {
                float4 bv1 = *reinterpret_cast<const float4*>(&Bs[kk][tx * TN + 4]);
                b2[2] = pack2(bv1.x, bv1.y);
                b2[3] = pack2(bv1.z, bv1.w);
            }
#pragma unroll
            for (int m = 0; m < 8; m++) {
                unsigned long long a2 = pack2(av[m], av[m]);
#pragma unroll
                for (int n = 0; n < TN / 2; n++) acc[m][n] = fma2(a2, b2[n], acc[m][n]);
            }
        }
        __syncthreads();
    }

    // epilogue: bias + gelu, float2 stores
#pragma unroll
    for (int m = 0; m < 8; m++) {
        int row = rowBase + ty * 8 + m;
#pragma unroll
        for (int n = 0; n < TN / 2; n++) {
            int col = colBase + tx * TN + n * 2;
            float2 v = unpack2(acc[m][n]);
            float2 o;
            o.x = gelu_tanh(v.x + bias[col]);
            o.y = gelu_tanh(v.y + bias[col + 1]);
            *reinterpret_cast<float2*>(&O[(size_t)row * Nn + col]) = o;
        }
    }
}

// ---------------- prep: zero accumulators, code norms ----------------
__global__ void prep_kernel(const float* __restrict__ emb) {
    int gid = blockIdx.x * 1024 + threadIdx.x;
    if (gid < DIM_C * NCODES) g_dw[gid] = 0.0f;
    if (blockIdx.x == 0) {
        int k = threadIdx.x;
        g_counts[k] = 0u;
        float s = 0.0f;
#pragma unroll
        for (int c = 0; c < DIM_C; c++) {
            float v = emb[(size_t)c * NCODES + k];
            s += v * v;
        }
        g_norms[k] = s;
        if (k == 0) g_loss[0] = 0.0f;
    }
}

// ---------------- VQ: distances + argmax + quantize + stats, fused ----------------
// score_k = 2*latent.emb_k - |emb_k|^2 ; argmax == reference argmax(-distances).
__global__ void __launch_bounds__(256, 2)
vq_kernel(const float* __restrict__ latent, const float* __restrict__ emb,
          float* __restrict__ outQ, float* __restrict__ outIdx) {
    constexpr int BM = 128, CD = 64, BN = 64, NT = NCODES / BN;  // 16 tiles
    __shared__ __align__(16) float As[BM][CD];       // latent tile, natural layout
    __shared__ __align__(16) union U {
        float b[CD][BN];                             // emb tile: b[c][code]
        struct {
            int idx[BM];
            float red[256];
        } fin;
    } sh;

    const int tid = threadIdx.x;
    const int tx = tid & 15;
    const int ty = tid >> 4;
    const int base = blockIdx.x * BM;

    // load latent tile (128x64 fp32)
#pragma unroll
    for (int it = 0; it < 8; it++) {
        int idx = tid + it * 256;  // 2048 float4
        int row = idx >> 4;
        int cq = idx & 15;
        *reinterpret_cast<float4*>(&As[row][cq * 4]) =
            *reinterpret_cast<const float4*>(&latent[(size_t)(base + row) * CD + cq * 4]);
    }

    float best[8];
    int bidx[8];
#pragma unroll
    for (int m = 0; m < 8; m++) {
        best[m] = -3.4e38f;
        bidx[m] = 0;
    }

    for (int t = 0; t < NT; t++) {
        __syncthreads();
#pragma unroll
        for (int it = 0; it < 4; it++) {
            int idx = tid + it * 256;  // 1024 float4
            int c = idx >> 4;
            int jq = idx & 15;
            *reinterpret_cast<float4*>(&sh.b[c][jq * 4]) =
                *reinterpret_cast<const float4*>(&emb[(size_t)c * NCODES + t * BN + jq * 4]);
        }
        __syncthreads();

        unsigned long long acc[8][2];
#pragma unroll
        for (int m = 0; m < 8; m++) { acc[m][0] = 0ull; acc[m][1] = 0ull; }

#pragma unroll 4
        for (int c = 0; c < CD; c++) {
            float4 bv = *reinterpret_cast<const float4*>(&sh.b[c][tx * 4]);
            unsigned long long b20 = pack2(bv.x, bv.y);
            unsigned long long b21 = pack2(bv.z, bv.w);
#pragma unroll
            for (int m = 0; m < 8; m++) {
                float a = As[ty * 8 + m][c];
                unsigned long long a2 = pack2(a, a);
                acc[m][0] = fma2(a2, b20, acc[m][0]);
                acc[m][1] = fma2(a2, b21, acc[m][1]);
            }
        }

        int cbase = t * BN + tx * 4;
        float n0 = __ldg(&g_norms[cbase + 0]);
        float n1 = __ldg(&g_norms[cbase + 1]);
        float n2 = __ldg(&g_norms[cbase + 2]);
        float n3 = __ldg(&g_norms[cbase + 3]);
#pragma unroll
        for (int m = 0; m < 8; m++) {
            float2 s0 = unpack2(acc[m][0]);
            float2 s1 = unpack2(acc[m][1]);
            float sc;
            sc = 2.0f * s0.x - n0; if (sc > best[m]) { best[m] = sc; bidx[m] = cbase + 0; }
            sc = 2.0f * s0.y - n1; if (sc > best[m]) { best[m] = sc; bidx[m] = cbase + 1; }
            sc = 2.0f * s1.x - n2; if (sc > best[m]) { best[m] = sc; bidx[m] = cbase + 2; }
            sc = 2.0f * s1.y - n3; if (sc > best[m]) { best[m] = sc; bidx[m] = cbase + 3; }
        }
    }

    // reduce across the 16 tx lanes (within-warp, xor widths 8..1; lane bit4 = ty parity)
#pragma unroll
    for (int m = 0; m < 8; m++) {
#pragma unroll
        for (int off = 8; off > 0; off >>= 1) {
            float ob = __shfl_xor_sync(0xffffffffu, best[m], off);
            int oi = __shfl_xor_sync(0xffffffffu, bidx[m], off);
            if (ob > best[m] || (ob == best[m] && oi < bidx[m])) { best[m] = ob; bidx[m] = oi; }
        }
    }
    __syncthreads();  // done with sh.b before union reuse
    if (tx == 0) {
#pragma unroll
        for (int m = 0; m < 8; m++) sh.fin.idx[ty * 8 + m] = bidx[m];
    }
    __syncthreads();

    // outputs: enc_idx + histogram
    if (tid < BM) {
        int id = sh.fin.idx[tid];
        outIdx[base + tid] = (float)id;
        atomicAdd(&g_counts[id], 1u);
    }
    // quantized (straight-through form l + (q - l)), loss partial, dw scatter
    float lsum = 0.0f;
#pragma unroll 8
    for (int it = 0; it < 32; it++) {
        int i = tid + it * 256;
        int row = i >> 6;
        int c = i & 63;
        int id = sh.fin.idx[row];
        float l = As[row][c];
        float q = __ldg(&emb[(size_t)c * NCODES + id]);
        outQ[(size_t)(base + row) * CD + c] = l + (q - l);
        float d = q - l;
        lsum += d * d;
        atomicAdd(&g_dw[(size_t)c * NCODES + id], l);
    }
    sh.fin.red[tid] = lsum;
    __syncthreads();
    for (int s = 128; s > 0; s >>= 1) {
        if (tid < s) sh.fin.red[tid] += sh.fin.red[tid + s];
        __syncthreads();
    }
    if (tid == 0) atomicAdd(&g_loss[0], sh.fin.red[0]);
}

// ---------------- finalize: EMA updates, loss, perplexity, new embeddings ----------------
__global__ void __launch_bounds__(1024)
finalize_kernel(const float* __restrict__ ema_cluster,
                const float* __restrict__ ema_dw,
                float* __restrict__ out) {
    constexpr size_t LOSS_OFF = (size_t)NTOK * DIM_C;
    constexpr size_t PERP_OFF = LOSS_OFF + 1;
    constexpr size_t IDX_OFF = PERP_OFF + 1;
    constexpr size_t EMB_OFF = IDX_OFF + (size_t)NTOK;

    __shared__ float red[1024];
    int k = threadIdx.x;
    float debias = (float)(1.0 - pow(0.99, 1001.0));  // 1 - decay^(counter+1)

    float cnt = (float)g_counts[k];
    float clh = ema_cluster[k] * DECAY_F + cnt * (1.0f - DECAY_F);
    float cs = clh / debias;

    red[k] = cs;
    __syncthreads();
    for (int s = 512; s > 0; s >>= 1) {
        if (k < s) red[k] += red[k + s];
        __syncthreads();
    }
    float n = red[0];
    __syncthreads();

    float p = cnt / (float)NTOK;
    red[k] = p * logf(p + 1e-10f);
    __syncthreads();
    for (int s = 512; s > 0; s >>= 1) {
        if (k < s) red[k] += red[k + s];
        __syncthreads();
    }
    float pl = red[0];

    float stable = (cs + 1e-5f) / (n + (float)NCODES * 1e-5f) * n;
#pragma unroll 4
    for (int c = 0; c < DIM_C; c++) {
        size_t i = (size_t)c * NCODES + k;
        float upd = (ema_dw[i] * DECAY_F + g_dw[i] * (1.0f - DECAY_F)) / debias;
        out[EMB_OFF + i] = upd / stable;
    }
    if (k == 0) {
        out[LOSS_OFF] = 0.25f * (g_loss[0] / ((float)NTOK * (float)DIM_C));
        out[PERP_OFF] = expf(-pl);
    }
}

// ---------------- launch ----------------
extern "C" void kernel_launch(void* const* d_in, const int* in_sizes, int n_in,
                              void* d_out, int out_size) {
    const float* states = (const float*)d_in[0];
    const float* w_se = (const float*)d_in[1];
    const float* b_se = (const float*)d_in[2];
    const float* w0 = (const float*)d_in[3];
    const float* b0 = (const float*)d_in[4];
    const float* w1 = (const float*)d_in[5];
    const float* b1 = (const float*)d_in[6];
    const float* w2 = (const float*)d_in[7];
    const float* b2 = (const float*)d_in[8];
    const float* emb = (const float*)d_in[9];
    const float* ema_cluster = (const float*)d_in[10];
    const float* ema_dw = (const float*)d_in[11];
    float* out = (float*)d_out;

    float *bufA, *bufB, *lat;
    cudaGetSymbolAddress((void**)&bufA, g_bufA);
    cudaGetSymbolAddress((void**)&bufB, g_bufB);
    cudaGetSymbolAddress((void**)&lat, g_latent);

    const size_t IDX_OFF = (size_t)NTOK * DIM_C + 2;

    dim3 blk(256);
    prep_kernel<<<64, 1024>>>(emb);
    sgemm_bias_gelu<128, 8><<<dim3(DIM_E / 128, NTOK / 128), blk>>>(
        states, w_se, b_se, bufA, NTOK, DIM_E, DIM_D);
    sgemm_bias_gelu<128, 8><<<dim3(DIM_H / 128, NTOK / 128), blk>>>(
        bufA, w0, b0, bufB, NTOK, DIM_H, DIM_E);
    sgemm_bias_gelu<128, 8><<<dim3(DIM_H / 128, NTOK / 128), blk>>>(
        bufB, w1, b1, bufA, NTOK, DIM_H, DIM_H);
    sgemm_bias_gelu<64, 4><<<dim3(1, NTOK / 128), blk>>>(
        bufA, w2, b2, lat, NTOK, DIM_C, DIM_H);
    vq_kernel<<<NTOK / 128, blk>>>(lat, emb, out /*quantized*/, out + IDX_OFF);
    finalize_kernel<<<1, 1024>>>(ema_cluster, ema_dw, out);
}

// round 5
// speedup vs baseline: 1.0406x; 1.0406x over previous
#include <cuda_runtime.h>
#include <cstdint>
#include <cstddef>

// ---------------- problem constants ----------------
#define NTOK   98304      // 32768 * 3 tokens
#define DIM_D  256
#define DIM_E  512
#define DIM_H  512
#define DIM_C  64
#define NCODES 1024
#define DECAY_F 0.99f

// ---------------- scratch (device globals; no allocs allowed) ----------------
__device__ float g_bufA[NTOK * DIM_E];     // 201 MB
__device__ float g_bufB[NTOK * DIM_H];     // 201 MB
__device__ float g_latent[NTOK * DIM_C];   // 25 MB
__device__ float g_dw[DIM_C * NCODES];
__device__ unsigned int g_counts[NCODES];
__device__ float g_norms[NCODES];
__device__ float g_loss[1];

// ---------------- f32x2 packed-FP32 helpers (Blackwell FFMA2 path) ----------------
__device__ __forceinline__ unsigned long long pack2(float lo, float hi) {
    unsigned long long r;
    asm("mov.b64 %0, {%1, %2};" : "=l"(r) : "f"(lo), "f"(hi));
    return r;
}
__device__ __forceinline__ unsigned long long fma2(unsigned long long a,
                                                   unsigned long long b,
                                                   unsigned long long c) {
    unsigned long long d;
    asm("fma.rn.f32x2 %0, %1, %2, %3;" : "=l"(d) : "l"(a), "l"(b), "l"(c));
    return d;
}
__device__ __forceinline__ float2 unpack2(unsigned long long v) {
    float lo, hi;
    asm("mov.b64 {%0, %1}, %2;" : "=f"(lo), "=f"(hi) : "l"(v));
    return make_float2(lo, hi);
}

__device__ __forceinline__ float gelu_tanh(float x) {
    // jax.nn.gelu approximate=True
    float x3 = x * x * x;
    float t = tanhf(0.7978845608028654f * (x + 0.044715f * x3));
    return 0.5f * x * (1.0f + t);
}

__device__ __forceinline__ uint32_t smem_u32(const void* p) {
    uint32_t a;
    asm("{ .reg .u64 t; cvta.to.shared.u64 t, %1; cvt.u32.u64 %0, t; }"
        : "=r"(a) : "l"(p));
    return a;
}
__device__ __forceinline__ void cp_async16(uint32_t saddr, const void* gptr) {
    asm volatile("cp.async.ca.shared.global [%0], [%1], 16;"
                 :: "r"(saddr), "l"(gptr) : "memory");
}
#define CP_COMMIT() asm volatile("cp.async.commit_group;" ::: "memory")
#define CP_WAIT0()  asm volatile("cp.async.wait_group 0;" ::: "memory")

// ---------------- pipelined fused SGEMM + bias + gelu (fp32 FFMA2) ----------------
// C[M,N] = gelu(A[M,K] @ W[K,N] + bias[N]), all fp32 row-major.
// BM=128, BK=16, 256 threads; per-thread 8 rows x TN cols, n-pair packed f32x2 accs.
// 2-stage pipeline: A via LDG(+2)->transposed STS(+1), B via cp.async(+1).
// Per-thread FFMA chain is k-sequential with identical operands to the R1 kernel
// => bit-identical outputs.
template <int BN, int TN>
__global__ void __launch_bounds__(256, 2)
sgemm_bias_gelu(const float* __restrict__ A, const float* __restrict__ W,
                const float* __restrict__ bias, float* __restrict__ O,
                int M, int Nn, int Kd) {
    constexpr int BM = 128, BK = 16;
    constexpr int ASTF = BK * (BM + 4);   // 2112 floats per stage
    constexpr int BSTF = BK * (BN + 4);
    constexpr int STAGEF = ASTF + BSTF;

    __shared__ __align__(16) float smem[2 * STAGEF];

    const int tid = threadIdx.x;
    const int tx = tid & 15;        // column group
    const int ty = tid >> 4;        // row group
    const int rowBase = blockIdx.y * BM;
    const int colBase = blockIdx.x * BN;
    const uint32_t sbase = smem_u32(smem);
    const int T = Kd / BK;

    unsigned long long acc[8][TN / 2];
#pragma unroll
    for (int m = 0; m < 8; m++)
#pragma unroll
        for (int n = 0; n < TN / 2; n++) acc[m][n] = 0ull;

    float4 areg[2];

#define LDG_A(t)                                                                \
    {                                                                           \
        _Pragma("unroll") for (int i = 0; i < 2; i++) {                         \
            int idx = tid + i * 256;                                            \
            int r = idx >> 2, kq = idx & 3;                                     \
            areg[i] = *reinterpret_cast<const float4*>(                         \
                &A[(size_t)(rowBase + r) * Kd + (t) * BK + kq * 4]);            \
        }                                                                       \
    }

#define STS_A(s)  /* transposed: As[k][m] */                                    \
    {                                                                           \
        float* As = smem + (s) * STAGEF;                                        \
        _Pragma("unroll") for (int i = 0; i < 2; i++) {                         \
            int idx = tid + i * 256;                                            \
            int r = idx >> 2, kq = idx & 3;                                     \
            float4 v = areg[i];                                                 \
            As[(kq * 4 + 0) * (BM + 4) + r] = v.x;                              \
            As[(kq * 4 + 1) * (BM + 4) + r] = v.y;                              \
            As[(kq * 4 + 2) * (BM + 4) + r] = v.z;                              \
            As[(kq * 4 + 3) * (BM + 4) + r] = v.w;                              \
        }                                                                       \
    }

#define CP_B(t, s)                                                              \
    {                                                                           \
        uint32_t bb = sbase + ((s) * STAGEF + ASTF) * 4;                        \
        constexpr int CHUNKS = BK * BN / 4;                                     \
        _Pragma("unroll") for (int i = 0; i < CHUNKS / 256; i++) {              \
            int idx = tid + i * 256;                                            \
            int krow = idx / (BN / 4);                                          \
            int nq = idx % (BN / 4);                                            \
            cp_async16(bb + (uint32_t)(krow * (BN + 4) + nq * 4) * 4,           \
                       &W[(size_t)((t) * BK + krow) * Nn + colBase + nq * 4]);  \
        }                                                                       \
    }

    // prologue
    LDG_A(0);
    CP_B(0, 0);
    CP_COMMIT();
    STS_A(0);
    if (T > 1) LDG_A(1);
    CP_WAIT0();
    __syncthreads();

    for (int t = 0; t < T; t++) {
        const int s = t & 1;
        if (t + 1 < T) {
            STS_A(s ^ 1);
            CP_B(t + 1, s ^ 1);
            CP_COMMIT();
        }
        if (t + 2 < T) LDG_A(t + 2);

        // compute stage s (identical arithmetic to round-1 kernel)
        {
            const float* As = smem + s * STAGEF;
            const float* Bs = As + ASTF;
#pragma unroll
            for (int kk = 0; kk < BK; kk++) {
                float4 a0 = *reinterpret_cast<const float4*>(&As[kk * (BM + 4) + ty * 8]);
                float4 a1 = *reinterpret_cast<const float4*>(&As[kk * (BM + 4) + ty * 8 + 4]);
                float av[8] = {a0.x, a0.y, a0.z, a0.w, a1.x, a1.y, a1.z, a1.w};
                unsigned long long b2[TN / 2];
                float4 bv0 = *reinterpret_cast<const float4*>(&Bs[kk * (BN + 4) + tx * TN]);
                b2[0] = pack2(bv0.x, bv0.y);
                b2[1] = pack2(bv0.z, bv0.w);
                if constexpr (TN == 8) {
                    float4 bv1 =
                        *reinterpret_cast<const float4*>(&Bs[kk * (BN + 4) + tx * TN + 4]);
                    b2[2] = pack2(bv1.x, bv1.y);
                    b2[3] = pack2(bv1.z, bv1.w);
                }
#pragma unroll
                for (int m = 0; m < 8; m++) {
                    unsigned long long a2 = pack2(av[m], av[m]);
#pragma unroll
                    for (int n = 0; n < TN / 2; n++) acc[m][n] = fma2(a2, b2[n], acc[m][n]);
                }
            }
        }
        if (t + 1 < T) CP_WAIT0();
        __syncthreads();
    }

    // epilogue: bias + gelu, float2 stores
#pragma unroll
    for (int m = 0; m < 8; m++) {
        int row = rowBase + ty * 8 + m;
#pragma unroll
        for (int n = 0; n < TN / 2; n++) {
            int col = colBase + tx * TN + n * 2;
            float2 v = unpack2(acc[m][n]);
            float2 o;
            o.x = gelu_tanh(v.x + bias[col]);
            o.y = gelu_tanh(v.y + bias[col + 1]);
            *reinterpret_cast<float2*>(&O[(size_t)row * Nn + col]) = o;
        }
    }
#undef LDG_A
#undef STS_A
#undef CP_B
}

// ---------------- prep: zero accumulators, code norms ----------------
__global__ void prep_kernel(const float* __restrict__ emb) {
    int gid = blockIdx.x * 1024 + threadIdx.x;
    if (gid < DIM_C * NCODES) g_dw[gid] = 0.0f;
    if (blockIdx.x == 0) {
        int k = threadIdx.x;
        g_counts[k] = 0u;
        float s = 0.0f;
#pragma unroll
        for (int c = 0; c < DIM_C; c++) {
            float v = emb[(size_t)c * NCODES + k];
            s += v * v;
        }
        g_norms[k] = s;
        if (k == 0) g_loss[0] = 0.0f;
    }
}

// ---------------- VQ: distances + argmax + quantize + stats, fused ----------------
__global__ void __launch_bounds__(256, 2)
vq_kernel(const float* __restrict__ latent, const float* __restrict__ emb,
          float* __restrict__ outQ, float* __restrict__ outIdx) {
    constexpr int BM = 128, CD = 64, BN = 64, NT = NCODES / BN;  // 16 tiles
    __shared__ __align__(16) float As[BM][CD];
    __shared__ __align__(16) union U {
        float b[CD][BN];
        struct {
            int idx[BM];
            float red[256];
        } fin;
    } sh;

    const int tid = threadIdx.x;
    const int tx = tid & 15;
    const int ty = tid >> 4;
    const int base = blockIdx.x * BM;

#pragma unroll
    for (int it = 0; it < 8; it++) {
        int idx = tid + it * 256;
        int row = idx >> 4;
        int cq = idx & 15;
        *reinterpret_cast<float4*>(&As[row][cq * 4]) =
            *reinterpret_cast<const float4*>(&latent[(size_t)(base + row) * CD + cq * 4]);
    }

    float best[8];
    int bidx[8];
#pragma unroll
    for (int m = 0; m < 8; m++) { best[m] = -3.4e38f; bidx[m] = 0; }

    for (int t = 0; t < NT; t++) {
        __syncthreads();
#pragma unroll
        for (int it = 0; it < 4; it++) {
            int idx = tid + it * 256;
            int c = idx >> 4;
            int jq = idx & 15;
            *reinterpret_cast<float4*>(&sh.b[c][jq * 4]) =
                *reinterpret_cast<const float4*>(&emb[(size_t)c * NCODES + t * BN + jq * 4]);
        }
        __syncthreads();

        unsigned long long acc[8][2];
#pragma unroll
        for (int m = 0; m < 8; m++) { acc[m][0] = 0ull; acc[m][1] = 0ull; }

#pragma unroll 4
        for (int c = 0; c < CD; c++) {
            float4 bv = *reinterpret_cast<const float4*>(&sh.b[c][tx * 4]);
            unsigned long long b20 = pack2(bv.x, bv.y);
            unsigned long long b21 = pack2(bv.z, bv.w);
#pragma unroll
            for (int m = 0; m < 8; m++) {
                float a = As[ty * 8 + m][c];
                unsigned long long a2 = pack2(a, a);
                acc[m][0] = fma2(a2, b20, acc[m][0]);
                acc[m][1] = fma2(a2, b21, acc[m][1]);
            }
        }

        int cbase = t * BN + tx * 4;
        float n0 = __ldg(&g_norms[cbase + 0]);
        float n1 = __ldg(&g_norms[cbase + 1]);
        float n2 = __ldg(&g_norms[cbase + 2]);
        float n3 = __ldg(&g_norms[cbase + 3]);
#pragma unroll
        for (int m = 0; m < 8; m++) {
            float2 s0 = unpack2(acc[m][0]);
            float2 s1 = unpack2(acc[m][1]);
            float sc;
            sc = 2.0f * s0.x - n0; if (sc > best[m]) { best[m] = sc; bidx[m] = cbase + 0; }
            sc = 2.0f * s0.y - n1; if (sc > best[m]) { best[m] = sc; bidx[m] = cbase + 1; }
            sc = 2.0f * s1.x - n2; if (sc > best[m]) { best[m] = sc; bidx[m] = cbase + 2; }
            sc = 2.0f * s1.y - n3; if (sc > best[m]) { best[m] = sc; bidx[m] = cbase + 3; }
        }
    }

#pragma unroll
    for (int m = 0; m < 8; m++) {
#pragma unroll
        for (int off = 8; off > 0; off >>= 1) {
            float ob = __shfl_xor_sync(0xffffffffu, best[m], off);
            int oi = __shfl_xor_sync(0xffffffffu, bidx[m], off);
            if (ob > best[m] || (ob == best[m] && oi < bidx[m])) { best[m] = ob; bidx[m] = oi; }
        }
    }
    __syncthreads();
    if (tx == 0) {
#pragma unroll
        for (int m = 0; m < 8; m++) sh.fin.idx[ty * 8 + m] = bidx[m];
    }
    __syncthreads();

    if (tid < BM) {
        int id = sh.fin.idx[tid];
        outIdx[base + tid] = (float)id;
        atomicAdd(&g_counts[id], 1u);
    }
    float lsum = 0.0f;
#pragma unroll 8
    for (int it = 0; it < 32; it++) {
        int i = tid + it * 256;
        int row = i >> 6;
        int c = i & 63;
        int id = sh.fin.idx[row];
        float l = As[row][c];
        float q = __ldg(&emb[(size_t)c * NCODES + id]);
        outQ[(size_t)(base + row) * CD + c] = l + (q - l);
        float d = q - l;
        lsum += d * d;
        atomicAdd(&g_dw[(size_t)c * NCODES + id], l);
    }
    sh.fin.red[tid] = lsum;
    __syncthreads();
    for (int s = 128; s > 0; s >>= 1) {
        if (tid < s) sh.fin.red[tid] += sh.fin.red[tid + s];
        __syncthreads();
    }
    if (tid == 0) atomicAdd(&g_loss[0], sh.fin.red[0]);
}

// ---------------- finalize: EMA updates, loss, perplexity, new embeddings ----------------
__global__ void __launch_bounds__(1024)
finalize_kernel(const float* __restrict__ ema_cluster,
                const float* __restrict__ ema_dw,
                float* __restrict__ out) {
    constexpr size_t LOSS_OFF = (size_t)NTOK * DIM_C;
    constexpr size_t PERP_OFF = LOSS_OFF + 1;
    constexpr size_t IDX_OFF = PERP_OFF + 1;
    constexpr size_t EMB_OFF = IDX_OFF + (size_t)NTOK;

    __shared__ float red[1024];
    int k = threadIdx.x;
    float debias = (float)(1.0 - pow(0.99, 1001.0));  // 1 - decay^(counter+1)

    float cnt = (float)g_counts[k];
    float clh = ema_cluster[k] * DECAY_F + cnt * (1.0f - DECAY_F);
    float cs = clh / debias;

    red[k] = cs;
    __syncthreads();
    for (int s = 512; s > 0; s >>= 1) {
        if (k < s) red[k] += red[k + s];
        __syncthreads();
    }
    float n = red[0];
    __syncthreads();

    float p = cnt / (float)NTOK;
    red[k] = p * logf(p + 1e-10f);
    __syncthreads();
    for (int s = 512; s > 0; s >>= 1) {
        if (k < s) red[k] += red[k + s];
        __syncthreads();
    }
    float pl = red[0];

    float stable = (cs + 1e-5f) / (n + (float)NCODES * 1e-5f) * n;
#pragma unroll 4
    for (int c = 0; c < DIM_C; c++) {
        size_t i = (size_t)c * NCODES + k;
        float upd = (ema_dw[i] * DECAY_F + g_dw[i] * (1.0f - DECAY_F)) / debias;
        out[EMB_OFF + i] = upd / stable;
    }
    if (k == 0) {
        out[LOSS_OFF] = 0.25f * (g_loss[0] / ((float)NTOK * (float)DIM_C));
        out[PERP_OFF] = expf(-pl);
    }
}

// ---------------- launch ----------------
extern "C" void kernel_launch(void* const* d_in, const int* in_sizes, int n_in,
                              void* d_out, int out_size) {
    const float* states = (const float*)d_in[0];
    const float* w_se = (const float*)d_in[1];
    const float* b_se = (const float*)d_in[2];
    const float* w0 = (const float*)d_in[3];
    const float* b0 = (const float*)d_in[4];
    const float* w1 = (const float*)d_in[5];
    const float* b1 = (const float*)d_in[6];
    const float* w2 = (const float*)d_in[7];
    const float* b2 = (const float*)d_in[8];
    const float* emb = (const float*)d_in[9];
    const float* ema_cluster = (const float*)d_in[10];
    const float* ema_dw = (const float*)d_in[11];
    float* out = (float*)d_out;

    float *bufA, *bufB, *lat;
    cudaGetSymbolAddress((void**)&bufA, g_bufA);
    cudaGetSymbolAddress((void**)&bufB, g_bufB);
    cudaGetSymbolAddress((void**)&lat, g_latent);

    const size_t IDX_OFF = (size_t)NTOK * DIM_C + 2;

    dim3 blk(256);
    prep_kernel<<<64, 1024>>>(emb);
    sgemm_bias_gelu<128, 8><<<dim3(DIM_E / 128, NTOK / 128), blk>>>(
        states, w_se, b_se, bufA, NTOK, DIM_E, DIM_D);
    sgemm_bias_gelu<128, 8><<<dim3(DIM_H / 128, NTOK / 128), blk>>>(
        bufA, w0, b0, bufB, NTOK, DIM_H, DIM_E);
    sgemm_bias_gelu<128, 8><<<dim3(DIM_H / 128, NTOK / 128), blk>>>(
        bufB, w1, b1, bufA, NTOK, DIM_H, DIM_H);
    sgemm_bias_gelu<64, 4><<<dim3(1, NTOK / 128), blk>>>(
        bufA, w2, b2, lat, NTOK, DIM_C, DIM_H);
    vq_kernel<<<NTOK / 128, 256>>>(lat, emb, out /*quantized*/, out + IDX_OFF);
    finalize_kernel<<<1, 1024>>>(ema_cluster, ema_dw, out);
}